// round 2
// baseline (speedup 1.0000x reference)
#include <cuda_runtime.h>

#define NSAMP 8192
#define CIN   512
#define CMID  256
#define COUT  128
#define KD    2048   // 128 * 16 pooled features
#define NOUT  1024
#define SPB   4      // samples per block in pool kernel

__device__ float g_W[CIN * COUT];      // w1 @ w2  (512 x 128)
__device__ float g_Kv[COUT];           // b1 @ w2 + b2
__device__ float g_pooled[(size_t)NSAMP * KD];  // 64 MB scratch

// ---------------------------------------------------------------------------
// Kernel A: fold weights.  W[c][o] = sum_m w1[c][m] * w2[m][o]
//           Kv[o] = b2[o] + sum_m b1[m] * w2[m][o]
// ---------------------------------------------------------------------------
__global__ void prep_kernel(const float* __restrict__ w1, const float* __restrict__ b1,
                            const float* __restrict__ w2, const float* __restrict__ b2) {
    const int o = threadIdx.x;       // 0..127
    const int c = blockIdx.x;        // 0..512 (last block does Kv)
    if (c < CIN) {
        float acc = 0.f;
        #pragma unroll 4
        for (int m = 0; m < CMID; m++)
            acc = fmaf(w1[c * CMID + m], w2[m * COUT + o], acc);
        g_W[c * COUT + o] = acc;
    } else {
        float acc = b2[o];
        for (int m = 0; m < CMID; m++)
            acc = fmaf(b1[m], w2[m * COUT + o], acc);
        g_Kv[o] = acc;
    }
}

// ---------------------------------------------------------------------------
// Kernel B: per-sample d = x(:,r,s) . W at the 4 live spatial positions,
//           then categorize roi and pool lazily-evaluated feat -> g_pooled
// feat(i,j):  b2        if i or j even
//             Kv+d      at (3,3),(3,7),(7,3),(7,7)
//             Kv        at other odd-odd
// ---------------------------------------------------------------------------
__global__ void __launch_bounds__(128) pool_kernel(const float* __restrict__ x,
                                                   const int*  __restrict__ rois,
                                                   const float* __restrict__ b2) {
    __shared__ __align__(16) float xs[CIN][SPB * 4 + 4];   // pad row to 20 floats
    const int o  = threadIdx.x;          // output channel, 0..127
    const int n0 = blockIdx.x * SPB;

    // stage x[n, c, {5,6,9,10}] (spatial (1,1),(1,2),(2,1),(2,2)) for SPB samples
    for (int i = threadIdx.x; i < SPB * CIN; i += 128) {
        const int s = i >> 9;            // i / 512
        const int c = i & (CIN - 1);
        const float* row = x + ((size_t)(n0 + s) * CIN + c) * 16;
        xs[c][s * 4 + 0] = __ldg(row + 5);
        xs[c][s * 4 + 1] = __ldg(row + 6);
        xs[c][s * 4 + 2] = __ldg(row + 9);
        xs[c][s * 4 + 3] = __ldg(row + 10);
    }
    __syncthreads();

    float d[SPB][4];
    #pragma unroll
    for (int s = 0; s < SPB; s++)
        #pragma unroll
        for (int p = 0; p < 4; p++) d[s][p] = 0.f;

    #pragma unroll 2
    for (int c = 0; c < CIN; c++) {
        const float w = g_W[c * COUT + o];
        #pragma unroll
        for (int s = 0; s < SPB; s++) {
            const float4 xv = *(const float4*)&xs[c][s * 4];
            d[s][0] = fmaf(xv.x, w, d[s][0]);
            d[s][1] = fmaf(xv.y, w, d[s][1]);
            d[s][2] = fmaf(xv.z, w, d[s][2]);
            d[s][3] = fmaf(xv.w, w, d[s][3]);
        }
    }

    const float b2o = b2[o];
    const float Ko  = g_Kv[o];

    #pragma unroll
    for (int s = 0; s < SPB; s++) {
        const int n = n0 + s;
        const int4 rr = *reinterpret_cast<const int4*>(rois + (size_t)n * 4);
        int y0 = rr.x, x0 = rr.y;
        const int y1 = rr.z, x1 = rr.w;
        const bool inb = ((y0 | x0 | y1 | x1) >= 0) &&
                         (y0 < 11) && (x0 < 11) && (y1 < 11) && (x1 < 11);
        const int h = y1 - y0, w = x1 - x0;
        int cat;
        if      (inb && h == 4 && w == 4) cat = 0;
        else if (inb && h == 8 && w == 8) cat = 1;
        else if (inb && h == 4 && w == 8) cat = 2;
        else if (inb && h == 6 && w == 8) cat = 3;
        else { cat = 4; y0 = 1; x0 = 1; }

        const float d00 = d[s][0], d01 = d[s][1], d10 = d[s][2], d11 = d[s][3];
        auto fv = [&](int i, int j) -> float {
            if (((i & 1) == 0) || ((j & 1) == 0)) return b2o;
            if ((i == 3 || i == 7) && (j == 3 || j == 7)) {
                const float dv = (i == 7) ? ((j == 7) ? d11 : d10)
                                          : ((j == 7) ? d01 : d00);
                return Ko + dv;
            }
            return Ko;
        };

        float ov[16];
        if (cat == 0) {
            for (int a = 0; a < 4; a++)
                for (int b = 0; b < 4; b++)
                    ov[a * 4 + b] = fv(y0 + a, x0 + b);
        } else if (cat == 1) {
            for (int a = 0; a < 4; a++)
                for (int b = 0; b < 4; b++) {
                    float m = fv(y0 + 2 * a,     x0 + 2 * b);
                    m = fmaxf(m, fv(y0 + 2 * a,     x0 + 2 * b + 1));
                    m = fmaxf(m, fv(y0 + 2 * a + 1, x0 + 2 * b));
                    m = fmaxf(m, fv(y0 + 2 * a + 1, x0 + 2 * b + 1));
                    ov[a * 4 + b] = m;
                }
        } else if (cat == 2) {
            for (int a = 0; a < 4; a++)
                for (int b = 0; b < 4; b++)
                    ov[a * 4 + b] = fmaxf(fv(y0 + a, x0 + 2 * b),
                                          fv(y0 + a, x0 + 2 * b + 1));
        } else if (cat == 3) {
            for (int a = 0; a < 4; a++) {
                const int r0 = (a == 0) ? y0 : (a == 3 ? y0 + 5 : y0 + 2 * a - 1);
                const int r1 = (a == 0) ? y0 : (a == 3 ? y0 + 5 : y0 + 2 * a);
                for (int b = 0; b < 4; b++) {
                    float m = fmaxf(fv(r0, x0 + 2 * b), fv(r0, x0 + 2 * b + 1));
                    m = fmaxf(m, fmaxf(fv(r1, x0 + 2 * b), fv(r1, x0 + 2 * b + 1)));
                    ov[a * 4 + b] = m;
                }
            }
        } else {  // cat 4: 3x3 window stride 2 starting at (1,1)
            for (int a = 0; a < 4; a++)
                for (int b = 0; b < 4; b++) {
                    float m = -3.402823466e+38f;
                    for (int dy = 0; dy < 3; dy++)
                        for (int dx = 0; dx < 3; dx++)
                            m = fmaxf(m, fv(1 + 2 * a + dy, 1 + 2 * b + dx));
                    ov[a * 4 + b] = m;
                }
        }

        float* dst = g_pooled + (size_t)n * KD + o * 16;
        *(float4*)(dst + 0)  = make_float4(ov[0],  ov[1],  ov[2],  ov[3]);
        *(float4*)(dst + 4)  = make_float4(ov[4],  ov[5],  ov[6],  ov[7]);
        *(float4*)(dst + 8)  = make_float4(ov[8],  ov[9],  ov[10], ov[11]);
        *(float4*)(dst + 12) = make_float4(ov[12], ov[13], ov[14], ov[15]);
    }
}

// ---------------------------------------------------------------------------
// Kernel C: C[8192,1024] = leaky( pooled[8192,2048] @ wl[2048,1024] + bl )
// 128x128 block tile, 8x8 per-thread micro tile, K-step 8.
// ---------------------------------------------------------------------------
__global__ void __launch_bounds__(256) sgemm_kernel(const float* __restrict__ B,
                                                    const float* __restrict__ bias,
                                                    float* __restrict__ C) {
    __shared__ float As[8][128];
    __shared__ float Bs[8][128];
    const int tid = threadIdx.x;
    const int bm  = blockIdx.y * 128;
    const int bn  = blockIdx.x * 128;
    const int tx  = tid & 15;
    const int ty  = tid >> 4;
    const int arow = tid >> 1;
    const int acol = (tid & 1) * 4;
    const int brow = tid >> 5;
    const int bcol = (tid & 31) * 4;
    const float* Aptr = g_pooled + (size_t)(bm + arow) * KD + acol;
    const float* Bptr = B + (size_t)brow * NOUT + bn + bcol;

    float acc[8][8];
    #pragma unroll
    for (int i = 0; i < 8; i++)
        #pragma unroll
        for (int j = 0; j < 8; j++) acc[i][j] = 0.f;

    for (int k0 = 0; k0 < KD; k0 += 8) {
        const float4 av = *(const float4*)(Aptr + k0);
        const float4 bv = *(const float4*)(Bptr + (size_t)k0 * NOUT);
        __syncthreads();
        As[acol + 0][arow] = av.x;
        As[acol + 1][arow] = av.y;
        As[acol + 2][arow] = av.z;
        As[acol + 3][arow] = av.w;
        *(float4*)&Bs[brow][bcol] = bv;
        __syncthreads();
        #pragma unroll
        for (int k = 0; k < 8; k++) {
            float a[8], b[8];
            *(float4*)(a)     = *(const float4*)&As[k][ty * 8];
            *(float4*)(a + 4) = *(const float4*)&As[k][ty * 8 + 4];
            *(float4*)(b)     = *(const float4*)&Bs[k][tx * 8];
            *(float4*)(b + 4) = *(const float4*)&Bs[k][tx * 8 + 4];
            #pragma unroll
            for (int i = 0; i < 8; i++)
                #pragma unroll
                for (int j = 0; j < 8; j++)
                    acc[i][j] = fmaf(a[i], b[j], acc[i][j]);
        }
    }

    float bs[8];
    #pragma unroll
    for (int j = 0; j < 8; j++) bs[j] = bias[bn + tx * 8 + j];

    #pragma unroll
    for (int i = 0; i < 8; i++) {
        const int row = bm + ty * 8 + i;
        float* crow = C + (size_t)row * NOUT + bn + tx * 8;
        float vv[8];
        #pragma unroll
        for (int j = 0; j < 8; j++) {
            const float v = acc[i][j] + bs[j];
            vv[j] = v > 0.f ? v : 0.01f * v;
        }
        *(float4*)(crow)     = make_float4(vv[0], vv[1], vv[2], vv[3]);
        *(float4*)(crow + 4) = make_float4(vv[4], vv[5], vv[6], vv[7]);
    }
}

// ---------------------------------------------------------------------------
extern "C" void kernel_launch(void* const* d_in, const int* in_sizes, int n_in,
                              void* d_out, int out_size) {
    const float* base = (const float*)d_in[0];   // (32,256,512,4,4)
    const int*   rois = (const int*)  d_in[1];   // (8192,4)
    const float* w1   = (const float*)d_in[2];   // (512,256)
    const float* b1   = (const float*)d_in[3];   // (256)
    const float* w2   = (const float*)d_in[4];   // (256,128)
    const float* b2   = (const float*)d_in[5];   // (128)
    const float* wl   = (const float*)d_in[6];   // (2048,1024)
    const float* bl   = (const float*)d_in[7];   // (1024)
    float* out = (float*)d_out;                  // (32,256,1024)

    prep_kernel<<<CIN + 1, COUT>>>(w1, b1, w2, b2);
    pool_kernel<<<NSAMP / SPB, 128>>>(base, rois, b2);
    sgemm_kernel<<<dim3(NOUT / 128, NSAMP / 128), 256>>>(wl, bl, out);
}

// round 3
// speedup vs baseline: 1.7238x; 1.7238x over previous
#include <cuda_runtime.h>
#include <cstdint>

#define NSAMP 8192
#define CIN   512
#define CMID  256
#define COUT  128
#define KD    2048   // 128 * 16 pooled features
#define NOUT  1024
#define SPB   4      // samples per block in pool kernel

__device__ float g_W[CIN * COUT];      // w1 @ w2  (512 x 128)
__device__ float g_Kv[COUT];           // b1 @ w2 + b2
__device__ float g_pooled[(size_t)NSAMP * KD];  // 64 MB scratch

// ---------------------------------------------------------------------------
// Kernel A: fold weights.  W[c][o] = sum_m w1[c][m] * w2[m][o]
//           Kv[o] = b2[o] + sum_m b1[m] * w2[m][o]
// 4 accumulators to break the lat-4 FMA dependency chain.
// ---------------------------------------------------------------------------
__global__ void prep_kernel(const float* __restrict__ w1, const float* __restrict__ b1,
                            const float* __restrict__ w2, const float* __restrict__ b2) {
    const int o = threadIdx.x;       // 0..127
    const int c = blockIdx.x;        // 0..512 (last block does Kv)
    if (c < CIN) {
        float a0 = 0.f, a1 = 0.f, a2 = 0.f, a3 = 0.f;
        const float* w1r = w1 + c * CMID;
        #pragma unroll 4
        for (int m = 0; m < CMID; m += 4) {
            a0 = fmaf(w1r[m + 0], w2[(m + 0) * COUT + o], a0);
            a1 = fmaf(w1r[m + 1], w2[(m + 1) * COUT + o], a1);
            a2 = fmaf(w1r[m + 2], w2[(m + 2) * COUT + o], a2);
            a3 = fmaf(w1r[m + 3], w2[(m + 3) * COUT + o], a3);
        }
        g_W[c * COUT + o] = (a0 + a1) + (a2 + a3);
    } else {
        float a0 = b2[o], a1 = 0.f, a2 = 0.f, a3 = 0.f;
        for (int m = 0; m < CMID; m += 4) {
            a0 = fmaf(b1[m + 0], w2[(m + 0) * COUT + o], a0);
            a1 = fmaf(b1[m + 1], w2[(m + 1) * COUT + o], a1);
            a2 = fmaf(b1[m + 2], w2[(m + 2) * COUT + o], a2);
            a3 = fmaf(b1[m + 3], w2[(m + 3) * COUT + o], a3);
        }
        g_Kv[o] = (a0 + a1) + (a2 + a3);
    }
}

// ---------------------------------------------------------------------------
// Kernel B: per-sample d = x(:,r,s) . W at the 4 live spatial positions,
//           then categorize roi and pool lazily-evaluated feat -> g_pooled
// feat(i,j):  b2        if i or j even
//             Kv+d      at (3,3),(3,7),(7,3),(7,7)
//             Kv        at other odd-odd
// ---------------------------------------------------------------------------
__global__ void __launch_bounds__(128) pool_kernel(const float* __restrict__ x,
                                                   const int*  __restrict__ rois,
                                                   const float* __restrict__ b2) {
    __shared__ __align__(16) float xs[CIN][SPB * 4 + 4];   // pad row to 20 floats
    const int o  = threadIdx.x;          // output channel, 0..127
    const int n0 = blockIdx.x * SPB;

    // stage x[n, c, {5,6,9,10}] (spatial (1,1),(1,2),(2,1),(2,2)) for SPB samples
    for (int i = threadIdx.x; i < SPB * CIN; i += 128) {
        const int s = i >> 9;            // i / 512
        const int c = i & (CIN - 1);
        const float* row = x + ((size_t)(n0 + s) * CIN + c) * 16;
        xs[c][s * 4 + 0] = __ldg(row + 5);
        xs[c][s * 4 + 1] = __ldg(row + 6);
        xs[c][s * 4 + 2] = __ldg(row + 9);
        xs[c][s * 4 + 3] = __ldg(row + 10);
    }
    __syncthreads();

    float d[SPB][4];
    #pragma unroll
    for (int s = 0; s < SPB; s++)
        #pragma unroll
        for (int p = 0; p < 4; p++) d[s][p] = 0.f;

    #pragma unroll 2
    for (int c = 0; c < CIN; c++) {
        const float w = g_W[c * COUT + o];
        #pragma unroll
        for (int s = 0; s < SPB; s++) {
            const float4 xv = *(const float4*)&xs[c][s * 4];
            d[s][0] = fmaf(xv.x, w, d[s][0]);
            d[s][1] = fmaf(xv.y, w, d[s][1]);
            d[s][2] = fmaf(xv.z, w, d[s][2]);
            d[s][3] = fmaf(xv.w, w, d[s][3]);
        }
    }

    const float b2o = b2[o];
    const float Ko  = g_Kv[o];

    #pragma unroll
    for (int s = 0; s < SPB; s++) {
        const int n = n0 + s;
        const int4 rr = *reinterpret_cast<const int4*>(rois + (size_t)n * 4);
        int y0 = rr.x, x0 = rr.y;
        const int y1 = rr.z, x1 = rr.w;
        const bool inb = ((y0 | x0 | y1 | x1) >= 0) &&
                         (y0 < 11) && (x0 < 11) && (y1 < 11) && (x1 < 11);
        const int h = y1 - y0, w = x1 - x0;
        int cat;
        if      (inb && h == 4 && w == 4) cat = 0;
        else if (inb && h == 8 && w == 8) cat = 1;
        else if (inb && h == 4 && w == 8) cat = 2;
        else if (inb && h == 6 && w == 8) cat = 3;
        else { cat = 4; y0 = 1; x0 = 1; }

        const float d00 = d[s][0], d01 = d[s][1], d10 = d[s][2], d11 = d[s][3];
        auto fv = [&](int i, int j) -> float {
            if (((i & 1) == 0) || ((j & 1) == 0)) return b2o;
            if ((i == 3 || i == 7) && (j == 3 || j == 7)) {
                const float dv = (i == 7) ? ((j == 7) ? d11 : d10)
                                          : ((j == 7) ? d01 : d00);
                return Ko + dv;
            }
            return Ko;
        };

        float ov[16];
        if (cat == 0) {
            for (int a = 0; a < 4; a++)
                for (int b = 0; b < 4; b++)
                    ov[a * 4 + b] = fv(y0 + a, x0 + b);
        } else if (cat == 1) {
            for (int a = 0; a < 4; a++)
                for (int b = 0; b < 4; b++) {
                    float m = fv(y0 + 2 * a,     x0 + 2 * b);
                    m = fmaxf(m, fv(y0 + 2 * a,     x0 + 2 * b + 1));
                    m = fmaxf(m, fv(y0 + 2 * a + 1, x0 + 2 * b));
                    m = fmaxf(m, fv(y0 + 2 * a + 1, x0 + 2 * b + 1));
                    ov[a * 4 + b] = m;
                }
        } else if (cat == 2) {
            for (int a = 0; a < 4; a++)
                for (int b = 0; b < 4; b++)
                    ov[a * 4 + b] = fmaxf(fv(y0 + a, x0 + 2 * b),
                                          fv(y0 + a, x0 + 2 * b + 1));
        } else if (cat == 3) {
            for (int a = 0; a < 4; a++) {
                const int r0 = (a == 0) ? y0 : (a == 3 ? y0 + 5 : y0 + 2 * a - 1);
                const int r1 = (a == 0) ? y0 : (a == 3 ? y0 + 5 : y0 + 2 * a);
                for (int b = 0; b < 4; b++) {
                    float m = fmaxf(fv(r0, x0 + 2 * b), fv(r0, x0 + 2 * b + 1));
                    m = fmaxf(m, fmaxf(fv(r1, x0 + 2 * b), fv(r1, x0 + 2 * b + 1)));
                    ov[a * 4 + b] = m;
                }
            }
        } else {  // cat 4: 3x3 window stride 2 starting at (1,1)
            for (int a = 0; a < 4; a++)
                for (int b = 0; b < 4; b++) {
                    float m = -3.402823466e+38f;
                    for (int dy = 0; dy < 3; dy++)
                        for (int dx = 0; dx < 3; dx++)
                            m = fmaxf(m, fv(1 + 2 * a + dy, 1 + 2 * b + dx));
                    ov[a * 4 + b] = m;
                }
        }

        float* dst = g_pooled + (size_t)n * KD + o * 16;
        *(float4*)(dst + 0)  = make_float4(ov[0],  ov[1],  ov[2],  ov[3]);
        *(float4*)(dst + 4)  = make_float4(ov[4],  ov[5],  ov[6],  ov[7]);
        *(float4*)(dst + 8)  = make_float4(ov[8],  ov[9],  ov[10], ov[11]);
        *(float4*)(dst + 12) = make_float4(ov[12], ov[13], ov[14], ov[15]);
    }
}

// ---------------------------------------------------------------------------
// Kernel C: C[8192,1024] = leaky( pooled[8192,2048] @ wl[2048,1024] + bl )
// TF32 mma.sync path: 128x128x32 block tile, 8 warps (64x32 warp tiles),
// 2-stage cp.async double buffering. Accumulation in fp32.
// ---------------------------------------------------------------------------
#define BM 128
#define BN 128
#define BK 32
#define KTILES (KD / BK)      // 64
#define AS_STRIDE 36          // 32 + 4 pad (conflict-free, 16B aligned)
#define BS_STRIDE 136         // 128 + 8 pad
#define AS_SIZE (BM * AS_STRIDE)   // floats per stage
#define BS_SIZE (BK * BS_STRIDE)

__device__ __forceinline__ uint32_t f2tf32(float x) {
    uint32_t r;
    asm("cvt.rna.tf32.f32 %0, %1;" : "=r"(r) : "f"(x));
    return r;
}

__global__ void __launch_bounds__(256) sgemm_tf32(const float* __restrict__ Bmat,
                                                  const float* __restrict__ bias,
                                                  float* __restrict__ C) {
    extern __shared__ float smem[];
    float* As = smem;                   // [2][BM][AS_STRIDE]
    float* Bs = smem + 2 * AS_SIZE;     // [2][BK][BS_STRIDE]

    const int tid  = threadIdx.x;
    const int bm   = blockIdx.y * BM;
    const int bn   = blockIdx.x * BN;
    const int warp = tid >> 5;
    const int lane = tid & 31;
    const int grp  = lane >> 2;   // 0..7
    const int qd   = lane & 3;    // 0..3
    const int wm   = (warp >> 2) * 64;   // 0 / 64
    const int wn   = (warp & 3) * 32;    // 0 / 32 / 64 / 96

    // global-load assignments (16B cp.async chunks, fully coalesced)
    const float* Ag = g_pooled + (size_t)(bm + (tid >> 1)) * KD + (tid & 1) * 16;
    const float* Bg = Bmat + (size_t)(tid >> 3) * NOUT + bn + (tid & 7) * 16;
    const uint32_t As_dst = (uint32_t)__cvta_generic_to_shared(As) +
                            (((tid >> 1) * AS_STRIDE + (tid & 1) * 16) << 2);
    const uint32_t Bs_dst = (uint32_t)__cvta_generic_to_shared(Bs) +
                            (((tid >> 3) * BS_STRIDE + (tid & 7) * 16) << 2);

    auto load_stage = [&](int stage, int k0) {
        const uint32_t ad = As_dst + stage * (AS_SIZE << 2);
        const float*   ag = Ag + k0;
        #pragma unroll
        for (int j = 0; j < 4; j++)
            asm volatile("cp.async.cg.shared.global [%0], [%1], 16;\n"
                         :: "r"(ad + j * 16), "l"(ag + j * 4));
        const uint32_t bd = Bs_dst + stage * (BS_SIZE << 2);
        const float*   bg = Bg + (size_t)k0 * NOUT;
        #pragma unroll
        for (int j = 0; j < 4; j++)
            asm volatile("cp.async.cg.shared.global [%0], [%1], 16;\n"
                         :: "r"(bd + j * 16), "l"(bg + j * 4));
    };

    float acc[4][4][4];
    #pragma unroll
    for (int i = 0; i < 4; i++)
        #pragma unroll
        for (int j = 0; j < 4; j++)
            #pragma unroll
            for (int r = 0; r < 4; r++) acc[i][j][r] = 0.f;

    load_stage(0, 0);
    asm volatile("cp.async.commit_group;\n");
    asm volatile("cp.async.wait_group 0;\n");
    __syncthreads();

    for (int t = 0; t < KTILES; ++t) {
        const int stage = t & 1;
        if (t + 1 < KTILES) {
            load_stage((t + 1) & 1, (t + 1) * BK);
            asm volatile("cp.async.commit_group;\n");
        }
        const float* Asb = As + stage * AS_SIZE;
        const float* Bsb = Bs + stage * BS_SIZE;

        #pragma unroll
        for (int kk = 0; kk < 4; ++kk) {
            uint32_t af[4][4], bf[4][2];
            #pragma unroll
            for (int i = 0; i < 4; i++) {
                const float* p0 = Asb + (wm + i * 16 + grp) * AS_STRIDE + kk * 8 + qd;
                const float* p1 = p0 + 8 * AS_STRIDE;
                af[i][0] = f2tf32(p0[0]);
                af[i][1] = f2tf32(p1[0]);
                af[i][2] = f2tf32(p0[4]);
                af[i][3] = f2tf32(p1[4]);
            }
            #pragma unroll
            for (int j = 0; j < 4; j++) {
                const float* q0 = Bsb + (kk * 8 + qd) * BS_STRIDE + wn + j * 8 + grp;
                bf[j][0] = f2tf32(q0[0]);
                bf[j][1] = f2tf32(q0[4 * BS_STRIDE]);
            }
            #pragma unroll
            for (int i = 0; i < 4; i++)
                #pragma unroll
                for (int j = 0; j < 4; j++)
                    asm volatile(
                        "mma.sync.aligned.m16n8k8.row.col.f32.tf32.tf32.f32 "
                        "{%0,%1,%2,%3}, {%4,%5,%6,%7}, {%8,%9}, {%0,%1,%2,%3};\n"
                        : "+f"(acc[i][j][0]), "+f"(acc[i][j][1]),
                          "+f"(acc[i][j][2]), "+f"(acc[i][j][3])
                        : "r"(af[i][0]), "r"(af[i][1]), "r"(af[i][2]), "r"(af[i][3]),
                          "r"(bf[j][0]), "r"(bf[j][1]));
        }
        if (t + 1 < KTILES)
            asm volatile("cp.async.wait_group 0;\n");
        __syncthreads();
    }

    // epilogue: bias + leaky relu, float2 stores
    #pragma unroll
    for (int j = 0; j < 4; j++) {
        const int c = bn + wn + j * 8 + 2 * qd;
        const float bz0 = __ldg(bias + c);
        const float bz1 = __ldg(bias + c + 1);
        #pragma unroll
        for (int i = 0; i < 4; i++) {
            const int r = bm + wm + i * 16 + grp;
            float v0 = acc[i][j][0] + bz0; v0 = v0 > 0.f ? v0 : 0.01f * v0;
            float v1 = acc[i][j][1] + bz1; v1 = v1 > 0.f ? v1 : 0.01f * v1;
            float v2 = acc[i][j][2] + bz0; v2 = v2 > 0.f ? v2 : 0.01f * v2;
            float v3 = acc[i][j][3] + bz1; v3 = v3 > 0.f ? v3 : 0.01f * v3;
            *(float2*)(C + (size_t)r * NOUT + c)       = make_float2(v0, v1);
            *(float2*)(C + (size_t)(r + 8) * NOUT + c) = make_float2(v2, v3);
        }
    }
}

// ---------------------------------------------------------------------------
extern "C" void kernel_launch(void* const* d_in, const int* in_sizes, int n_in,
                              void* d_out, int out_size) {
    const float* base = (const float*)d_in[0];   // (32,256,512,4,4)
    const int*   rois = (const int*)  d_in[1];   // (8192,4)
    const float* w1   = (const float*)d_in[2];   // (512,256)
    const float* b1   = (const float*)d_in[3];   // (256)
    const float* w2   = (const float*)d_in[4];   // (256,128)
    const float* b2   = (const float*)d_in[5];   // (128)
    const float* wl   = (const float*)d_in[6];   // (2048,1024)
    const float* bl   = (const float*)d_in[7];   // (1024)
    float* out = (float*)d_out;                  // (32,256,1024)

    const size_t smem_bytes = (size_t)(2 * AS_SIZE + 2 * BS_SIZE) * sizeof(float);
    cudaFuncSetAttribute(sgemm_tf32, cudaFuncAttributeMaxDynamicSharedMemorySize,
                         (int)smem_bytes);

    prep_kernel<<<CIN + 1, COUT>>>(w1, b1, w2, b2);
    pool_kernel<<<NSAMP / SPB, 128>>>(base, rois, b2);
    sgemm_tf32<<<dim3(NOUT / BN, NSAMP / BM), 256, smem_bytes>>>(wl, bl, out);
}